// round 2
// baseline (speedup 1.0000x reference)
#include <cuda_runtime.h>

#define NMAX   50000
#define D      96
#define D4     24    // D/4 float4 per row

// ---------------- scratch (device globals; no allocation allowed) ----------
__device__ float4 g_pool[NMAX * D4];            // pooled features (19.2 MB)
__device__ float  g_sum[D];
__device__ float  g_sumsq[D];
__device__ __align__(16) float g_scale[D];
__device__ __align__(16) float g_shift[D];

// ---------------- K1: pooled = (1+eps)*feature; zero BN accumulators -------
__global__ void init_kernel(const float4* __restrict__ feat,
                            const float* __restrict__ eps, int n4) {
    int i = blockIdx.x * blockDim.x + threadIdx.x;
    if (i < D) { g_sum[i] = 0.f; g_sumsq[i] = 0.f; }
    if (i >= n4) return;
    float s = 1.0f + eps[0];
    float4 v = feat[i];
    v.x *= s; v.y *= s; v.z *= s; v.w *= s;
    g_pool[i] = v;
}

// ---------------- K2: edge scatter: pooled[dst] += feature[src] ------------
// one thread per (edge, float4-chunk); vector RED to cut LSU ops 4x
__global__ void scatter_kernel(const float4* __restrict__ feat,
                               const int* __restrict__ src,
                               const int* __restrict__ dst, int total) {
    int i = blockIdx.x * blockDim.x + threadIdx.x;
    if (i >= total) return;
    int e = i / D4;
    int j = i - e * D4;
    int s = __ldg(src + e);
    int d = __ldg(dst + e);
    float4 v = __ldg(feat + (long)s * D4 + j);
    float4* p = g_pool + (long)d * D4 + j;
    asm volatile("red.global.add.v4.f32 [%0], {%1,%2,%3,%4};"
                 :: "l"(p), "f"(v.x), "f"(v.y), "f"(v.z), "f"(v.w)
                 : "memory");
}

// ---------------- K3: fused  h2 = relu(pooled@W1+b1)@W2+b2  + BN stats -----
// 128 rows per block, 256 threads, each thread owns a 4x12 register tile.
#define TM 128
#define AS 100   // padded row stride for A tile (bank-conflict mitigation)

__global__ __launch_bounds__(256, 2)
void mlp_kernel(const float* __restrict__ W1, const float* __restrict__ b1,
                const float* __restrict__ W2, const float* __restrict__ b2,
                float* __restrict__ out, int n) {
    extern __shared__ float smem[];
    float* As    = smem;                 // TM * AS      = 12800 floats
    float* Ws    = smem + TM * AS;       // 96*96        =  9216 floats
    float* s_sum = Ws + D * D;           // 96
    float* s_sq  = s_sum + D;            // 96

    const int tid = threadIdx.x;
    const int tx  = tid & 7;             // 8 col groups * 12 cols = 96
    const int ty  = tid >> 3;            // 32 row groups * 4 rows = 128
    const int rb  = blockIdx.x * TM;

    if (tid < D) { s_sum[tid] = 0.f; s_sq[tid] = 0.f; }

    // cooperative load: A tile (pooled) and W1
    for (int i = tid; i < TM * D4; i += 256) {
        int r  = i / D4;
        int c4 = i - r * D4;
        float4 v = make_float4(0.f, 0.f, 0.f, 0.f);
        if (rb + r < n) v = g_pool[(rb + r) * D4 + c4];
        *(float4*)(As + r * AS + c4 * 4) = v;
    }
    for (int i = tid; i < (D * D) / 4; i += 256)
        ((float4*)Ws)[i] = ((const float4*)W1)[i];
    __syncthreads();

    float acc[4][12];
    #pragma unroll
    for (int r = 0; r < 4; r++)
        #pragma unroll
        for (int c = 0; c < 12; c++) acc[r][c] = 0.f;

    // ---- GEMM1 ----
    #pragma unroll 6
    for (int k4 = 0; k4 < D; k4 += 4) {
        float4 av[4];
        #pragma unroll
        for (int r = 0; r < 4; r++)
            av[r] = *(const float4*)(As + (ty * 4 + r) * AS + k4);
        #pragma unroll
        for (int kk = 0; kk < 4; kk++) {
            int k = k4 + kk;
            float4 w0 = *(const float4*)(Ws + k * D + tx * 12);
            float4 w1 = *(const float4*)(Ws + k * D + tx * 12 + 4);
            float4 w2 = *(const float4*)(Ws + k * D + tx * 12 + 8);
            float wv[12] = {w0.x,w0.y,w0.z,w0.w, w1.x,w1.y,w1.z,w1.w,
                            w2.x,w2.y,w2.z,w2.w};
            #pragma unroll
            for (int r = 0; r < 4; r++) {
                float a = (kk == 0) ? av[r].x : (kk == 1) ? av[r].y
                        : (kk == 2) ? av[r].z : av[r].w;
                #pragma unroll
                for (int c = 0; c < 12; c++)
                    acc[r][c] = fmaf(a, wv[c], acc[r][c]);
            }
        }
    }
    __syncthreads();   // everyone done reading As / Ws

    // write h1 = relu(acc + b1) back into As; stage W2
    #pragma unroll
    for (int c = 0; c < 12; c++) {
        float bb = __ldg(b1 + tx * 12 + c);
        #pragma unroll
        for (int r = 0; r < 4; r++)
            As[(ty * 4 + r) * AS + tx * 12 + c] = fmaxf(acc[r][c] + bb, 0.f);
    }
    for (int i = tid; i < (D * D) / 4; i += 256)
        ((float4*)Ws)[i] = ((const float4*)W2)[i];
    __syncthreads();

    #pragma unroll
    for (int r = 0; r < 4; r++)
        #pragma unroll
        for (int c = 0; c < 12; c++) acc[r][c] = 0.f;

    // ---- GEMM2 ----
    #pragma unroll 6
    for (int k4 = 0; k4 < D; k4 += 4) {
        float4 av[4];
        #pragma unroll
        for (int r = 0; r < 4; r++)
            av[r] = *(const float4*)(As + (ty * 4 + r) * AS + k4);
        #pragma unroll
        for (int kk = 0; kk < 4; kk++) {
            int k = k4 + kk;
            float4 w0 = *(const float4*)(Ws + k * D + tx * 12);
            float4 w1 = *(const float4*)(Ws + k * D + tx * 12 + 4);
            float4 w2 = *(const float4*)(Ws + k * D + tx * 12 + 8);
            float wv[12] = {w0.x,w0.y,w0.z,w0.w, w1.x,w1.y,w1.z,w1.w,
                            w2.x,w2.y,w2.z,w2.w};
            #pragma unroll
            for (int r = 0; r < 4; r++) {
                float a = (kk == 0) ? av[r].x : (kk == 1) ? av[r].y
                        : (kk == 2) ? av[r].z : av[r].w;
                #pragma unroll
                for (int c = 0; c < 12; c++)
                    acc[r][c] = fmaf(a, wv[c], acc[r][c]);
            }
        }
    }

    // ---- epilogue: +b2, store h2, reduce BN sums ----
    #pragma unroll
    for (int c = 0; c < 12; c++) {
        int col = tx * 12 + c;
        float bb = __ldg(b2 + col);
        float s = 0.f, s2 = 0.f;
        #pragma unroll
        for (int r = 0; r < 4; r++) {
            int row = rb + ty * 4 + r;
            float v = acc[r][c] + bb;
            if (row < n) {
                out[row * D + col] = v;
                s  += v;
                s2 += v * v;
            }
        }
        // reduce over the 4 lanes in this warp that share tx (lanes l, l^8, l^16, l^24)
        s  += __shfl_xor_sync(0xffffffffu, s, 8);
        s  += __shfl_xor_sync(0xffffffffu, s, 16);
        s2 += __shfl_xor_sync(0xffffffffu, s2, 8);
        s2 += __shfl_xor_sync(0xffffffffu, s2, 16);
        if ((tid & 31) < 8) {
            atomicAdd(&s_sum[col], s);
            atomicAdd(&s_sq[col], s2);
        }
    }
    __syncthreads();
    if (tid < D) {
        atomicAdd(&g_sum[tid],   s_sum[tid]);
        atomicAdd(&g_sumsq[tid], s_sq[tid]);
    }
}

// ---------------- K4: BN affine params from accumulated stats --------------
__global__ void finalize_kernel(const float* __restrict__ gamma,
                                const float* __restrict__ beta, float invN) {
    int d = threadIdx.x;
    if (d >= D) return;
    float mean = g_sum[d] * invN;
    float var  = g_sumsq[d] * invN - mean * mean;
    float rstd = rsqrtf(var + 1e-5f);
    float sc   = rstd * gamma[d];
    g_scale[d] = sc;
    g_shift[d] = beta[d] - mean * sc;
}

// ---------------- K5: out = relu(h2 * scale[col] + shift[col]) -------------
__global__ void apply_kernel(float4* __restrict__ out4, int n4) {
    int i = blockIdx.x * blockDim.x + threadIdx.x;
    if (i >= n4) return;
    int c4 = i % D4;
    float4 h  = out4[i];
    float4 sc = ((const float4*)g_scale)[c4];
    float4 sh = ((const float4*)g_shift)[c4];
    h.x = fmaxf(fmaf(h.x, sc.x, sh.x), 0.f);
    h.y = fmaxf(fmaf(h.y, sc.y, sh.y), 0.f);
    h.z = fmaxf(fmaf(h.z, sc.z, sh.z), 0.f);
    h.w = fmaxf(fmaf(h.w, sc.w, sh.w), 0.f);
    out4[i] = h;
}

// ---------------------------------------------------------------------------
extern "C" void kernel_launch(void* const* d_in, const int* in_sizes, int n_in,
                              void* d_out, int out_size) {
    const float* feature = (const float*)d_in[0];
    const int*   src     = (const int*)d_in[1];
    const int*   dst     = (const int*)d_in[2];
    const float* W1      = (const float*)d_in[3];
    const float* b1      = (const float*)d_in[4];
    const float* W2      = (const float*)d_in[5];
    const float* b2      = (const float*)d_in[6];
    const float* gamma   = (const float*)d_in[7];
    const float* beta    = (const float*)d_in[8];
    const float* eps     = (const float*)d_in[9];
    float* out = (float*)d_out;

    const int n  = in_sizes[0] / D;     // 50000
    const int E  = in_sizes[1];         // 800000
    const int n4 = n * D4;

    init_kernel<<<(n4 + 255) / 256, 256>>>((const float4*)feature, eps, n4);

    int total = E * D4;                  // 19.2M, fits in int
    scatter_kernel<<<(total + 255) / 256, 256>>>((const float4*)feature,
                                                 src, dst, total);

    const int SMEM = (TM * AS + D * D + 2 * D) * (int)sizeof(float); // 88832 B
    cudaFuncSetAttribute(mlp_kernel,
                         cudaFuncAttributeMaxDynamicSharedMemorySize, SMEM);
    mlp_kernel<<<(n + TM - 1) / TM, 256, SMEM>>>(W1, b1, W2, b2, out, n);

    finalize_kernel<<<1, 128>>>(gamma, beta, 1.0f / (float)n);

    apply_kernel<<<(n4 + 255) / 256, 256>>>((float4*)out, n4);
}